// round 7
// baseline (speedup 1.0000x reference)
#include <cuda_runtime.h>
#include <cstdint>

#define NTOK 65536
#define KCB  8192
#define DDIM 64
#define DECAYF 0.9f
#define EPSF 1e-5f

// ---- scratch (no allocation allowed) ----
__device__ float g_cnorm[KCB];
__device__ int   g_token[NTOK];
__device__ float g_counts[KCB];
__device__ float g_embed_sum[KCB * DDIM];
__device__ float g_qerr;
__device__ float g_nsum;
// transposed split codebook: rows 0-63 = tf32_hi(w[:,d]), rows 64-127 = tf32_lo
__device__ __align__(16) float g_w3t[(size_t)128 * KCB];

// ================= helpers =================
__device__ __forceinline__ uint32_t smem_u32(const void* p) {
    uint32_t a;
    asm("{ .reg .u64 t; cvta.to.shared.u64 t, %1; cvt.u32.u64 %0, t; }" : "=r"(a) : "l"(p));
    return a;
}
__device__ __forceinline__ uint32_t tf32r(float x) {
    uint32_t u; asm("cvt.rna.tf32.f32 %0, %1;" : "=r"(u) : "f"(x)); return u;
}
__device__ __forceinline__ void cp16(uint32_t dst, const void* src) {
    asm volatile("cp.async.ca.shared.global [%0], [%1], 16;" :: "r"(dst), "l"(src));
}
__device__ __forceinline__ void mma8(float* c, const uint32_t* a, uint32_t b0, uint32_t b1) {
    asm volatile("mma.sync.aligned.m16n8k8.row.col.f32.tf32.tf32.f32 "
        "{%0,%1,%2,%3},{%4,%5,%6,%7},{%8,%9},{%0,%1,%2,%3};"
        : "+f"(c[0]), "+f"(c[1]), "+f"(c[2]), "+f"(c[3])
        : "r"(a[0]), "r"(a[1]), "r"(a[2]), "r"(a[3]), "r"(b0), "r"(b1));
}

// ================= small kernels =================
__global__ void k_zero() {
    int i = blockIdx.x * blockDim.x + threadIdx.x;
    if (i < KCB * DDIM) g_embed_sum[i] = 0.0f;
    if (i < KCB)        g_counts[i]    = 0.0f;
    if (i == 0) { g_qerr = 0.0f; g_nsum = 0.0f; }
}

__global__ void k_cnorm(const float* __restrict__ w) {
    int warp = (blockIdx.x * blockDim.x + threadIdx.x) >> 5;
    int lane = threadIdx.x & 31;
    if (warp >= KCB) return;
    float v0 = w[warp * DDIM + lane];
    float v1 = w[warp * DDIM + 32 + lane];
    float s = v0 * v0 + v1 * v1;
    #pragma unroll
    for (int o = 16; o; o >>= 1) s += __shfl_xor_sync(0xffffffffu, s, o);
    if (lane == 0) g_cnorm[warp] = s;
}

// build g_w3t[k][c]: k<64 -> tf32_hi(w[c][k]); k>=64 -> tf32_lo(w[c][k-64])
__global__ void k_prep(const float* __restrict__ w) {
    int i = blockIdx.x * blockDim.x + threadIdx.x;
    if (i >= 128 * KCB) return;
    int k = i >> 13, c = i & (KCB - 1);
    float v = w[(size_t)c * DDIM + (k & 63)];
    uint32_t hi = tf32r(v);
    uint32_t out = (k < 64) ? hi : tf32r(v - __uint_as_float(hi));
    ((uint32_t*)g_w3t)[i] = out;
}

// ================= main tensor-core kernel =================
// 512 threads = 16 warps (4x4 grid). M=128 tokens, N-tile=128 codes, 64 tiles.
static constexpr int AST   = 132;                    // A row stride (floats)
static constexpr int BST   = 136;                    // B k-row stride (floats)
static constexpr int SM_A  = 0;                      // 128*132*4 = 67584
static constexpr int SM_B  = 67584;
static constexpr int B_BUF = 128 * BST * 4;          // 69632
static constexpr int SMEM_TC = SM_B + 2 * B_BUF;     // 206848

__global__ __launch_bounds__(512) void k_main_tc(const float* __restrict__ z) {
    extern __shared__ char smem[];
    float* As = (float*)(smem + SM_A);
    float* Bs = (float*)(smem + SM_B);
    const uint32_t sbB = smem_u32(Bs);

    const int tid  = threadIdx.x;
    const int lane = tid & 31, wid = tid >> 5;
    const int g    = lane >> 2, tg = lane & 3;
    const int wr   = wid & 3,  wc = wid >> 2;        // 4 token-rows x 4 code-cols
    const int tok0 = blockIdx.x * 128;

    // ---- stage A: z[128][64] -> hi cols 0-63, lo cols 64-127 ----
    #pragma unroll
    for (int i = 0; i < 4; i++) {
        int q = i * 512 + tid;                       // 2048 float4 total
        int row = q >> 4, c4 = q & 15;
        float4 v = *(const float4*)(z + (size_t)(tok0 + row) * DDIM + c4 * 4);
        float4 hi, lo;
        hi.x = __uint_as_float(tf32r(v.x)); lo.x = __uint_as_float(tf32r(v.x - hi.x));
        hi.y = __uint_as_float(tf32r(v.y)); lo.y = __uint_as_float(tf32r(v.y - hi.y));
        hi.z = __uint_as_float(tf32r(v.z)); lo.z = __uint_as_float(tf32r(v.z - hi.z));
        hi.w = __uint_as_float(tf32r(v.w)); lo.w = __uint_as_float(tf32r(v.w - hi.w));
        *(float4*)(As + row * AST + c4 * 4)      = hi;
        *(float4*)(As + row * AST + 64 + c4 * 4) = lo;
    }
    // ---- prefetch B tile 0 (128 codes x 128 k) ----
    #pragma unroll
    for (int i = 0; i < 8; i++) {
        int q = i * 512 + tid;                       // 4096 x 16B
        int k = q >> 5, seg = q & 31;
        cp16(sbB + (uint32_t)(k * BST + seg * 4) * 4,
             g_w3t + (size_t)k * KCB + seg * 4);
    }
    asm volatile("cp.async.commit_group;");
    __syncthreads();

    float bv[4];  int bix[4];
    #pragma unroll
    for (int r = 0; r < 4; r++) { bv[r] = 3.4e38f; bix[r] = 0; }

    for (int t = 0; t < 64; t++) {
        const int buf = t & 1;
        if (t < 63) {
            const uint32_t dstb = sbB + (uint32_t)(buf ^ 1) * B_BUF;
            const float* srcg = g_w3t + (t + 1) * 128;
            #pragma unroll
            for (int i = 0; i < 8; i++) {
                int q = i * 512 + tid;
                int k = q >> 5, seg = q & 31;
                cp16(dstb + (uint32_t)(k * BST + seg * 4) * 4,
                     srcg + (size_t)k * KCB + seg * 4);
            }
            asm volatile("cp.async.commit_group;");
            asm volatile("cp.async.wait_group 1;");
        } else {
            asm volatile("cp.async.wait_group 0;");
        }
        __syncthreads();

        const float* B = Bs + buf * (128 * BST);
        float acc[2][4][4];
        #pragma unroll
        for (int m = 0; m < 2; m++)
            #pragma unroll
            for (int nt = 0; nt < 4; nt++)
                #pragma unroll
                for (int c = 0; c < 4; c++) acc[m][nt][c] = 0.0f;

        // 3 K-blocks: (A hi x B hi), (A hi x B lo), (A lo x B hi)
        #pragma unroll
        for (int blk = 0; blk < 3; blk++) {
            const int abase = (blk == 2) ? 64 : 0;
            const int bbase = (blk == 1) ? 64 : 0;
            #pragma unroll
            for (int j = 0; j < 8; j++) {
                const int ca = abase + 8 * j;
                const int kb = bbase + 8 * j;
                uint32_t a[2][4];
                #pragma unroll
                for (int m = 0; m < 2; m++) {
                    const float* ap = As + (wr * 32 + m * 16 + g) * AST + ca + tg;
                    a[m][0] = __float_as_uint(ap[0]);
                    a[m][1] = __float_as_uint(ap[8 * AST]);
                    a[m][2] = __float_as_uint(ap[4]);
                    a[m][3] = __float_as_uint(ap[8 * AST + 4]);
                }
                #pragma unroll
                for (int nt = 0; nt < 4; nt++) {
                    const float* bp = B + (kb + tg) * BST + wc * 32 + nt * 8 + g;
                    uint32_t b0 = __float_as_uint(bp[0]);
                    uint32_t b1 = __float_as_uint(bp[4 * BST]);
                    mma8(acc[0][nt], a[0], b0, b1);
                    mma8(acc[1][nt], a[1], b0, b1);
                }
            }
        }

        // epilogue: dist = cn - 2*dot, running argmin (ascending codes = first-min)
        const int cb = t * 128;
        #pragma unroll
        for (int nt = 0; nt < 4; nt++) {
            const int col = cb + wc * 32 + nt * 8 + 2 * tg;
            const float2 c2 = __ldg((const float2*)(g_cnorm + col));
            #pragma unroll
            for (int m = 0; m < 2; m++) {
                #pragma unroll
                for (int h = 0; h < 2; h++) {
                    const int r = m * 2 + h;
                    float d0 = fmaf(-2.0f, acc[m][nt][h * 2 + 0], c2.x);
                    float d1 = fmaf(-2.0f, acc[m][nt][h * 2 + 1], c2.y);
                    if (d0 < bv[r]) { bv[r] = d0; bix[r] = col; }
                    if (d1 < bv[r]) { bv[r] = d1; bix[r] = col + 1; }
                }
            }
        }
        __syncthreads();
    }

    // combine across quad lanes (same token rows), tie-break smaller index
    #pragma unroll
    for (int r = 0; r < 4; r++) {
        float v = bv[r]; int ix = bix[r];
        #pragma unroll
        for (int o = 1; o < 4; o <<= 1) {
            float v2 = __shfl_xor_sync(0xffffffffu, v, o);
            int   i2 = __shfl_xor_sync(0xffffffffu, ix, o);
            if (v2 < v || (v2 == v && i2 < ix)) { v = v2; ix = i2; }
        }
        bv[r] = v; bix[r] = ix;
    }
    __syncthreads();
    float* sv = Bs;                     // [4 wc][128 rows]
    int*   si = (int*)(Bs + 512);
    if (tg == 0) {
        #pragma unroll
        for (int m = 0; m < 2; m++)
            #pragma unroll
            for (int h = 0; h < 2; h++) {
                int row = wr * 32 + m * 16 + g + 8 * h;
                sv[wc * 128 + row] = bv[m * 2 + h];
                si[wc * 128 + row] = bix[m * 2 + h];
            }
    }
    __syncthreads();
    if (tid < 128) {
        float v = sv[tid]; int ix = si[tid];
        #pragma unroll
        for (int c = 1; c < 4; c++) {
            float v2 = sv[c * 128 + tid];
            int   i2 = si[c * 128 + tid];
            if (v2 < v || (v2 == v && i2 < ix)) { v = v2; ix = i2; }
        }
        g_token[tok0 + tid] = ix;
    }
}

// ---------------- scatter: counts, embed_sum, quant error ----------------
__global__ void k_scatter(const float* __restrict__ z, const float* __restrict__ w) {
    __shared__ float qs[8];
    int warp = threadIdx.x >> 5;
    int lane = threadIdx.x & 31;
    int n = blockIdx.x * 8 + warp;
    int k = g_token[n];
    float z0 = z[(size_t)n * DDIM + lane];
    float z1 = z[(size_t)n * DDIM + 32 + lane];
    float w0 = w[(size_t)k * DDIM + lane];
    float w1 = w[(size_t)k * DDIM + 32 + lane];
    atomicAdd(&g_embed_sum[k * DDIM + lane], z0);
    atomicAdd(&g_embed_sum[k * DDIM + 32 + lane], z1);
    float d0 = w0 - z0, d1 = w1 - z1;
    float s = d0 * d0 + d1 * d1;
    #pragma unroll
    for (int o = 16; o; o >>= 1) s += __shfl_xor_sync(0xffffffffu, s, o);
    if (lane == 0) { qs[warp] = s; atomicAdd(&g_counts[k], 1.0f); }
    __syncthreads();
    if (threadIdx.x == 0) {
        float t = 0.0f;
        #pragma unroll
        for (int i = 0; i < 8; i++) t += qs[i];
        atomicAdd(&g_qerr, t);
    }
}

__global__ void k_ema1(const float* __restrict__ cs, float* __restrict__ out) {
    __shared__ float red[256];
    int k = blockIdx.x * blockDim.x + threadIdx.x;
    float ncs = cs[k] * DECAYF + (1.0f - DECAYF) * g_counts[k];
    out[1 + KCB * DDIM + k] = ncs;
    red[threadIdx.x] = ncs;
    __syncthreads();
    for (int s = 128; s; s >>= 1) {
        if (threadIdx.x < s) red[threadIdx.x] += red[threadIdx.x + s];
        __syncthreads();
    }
    if (threadIdx.x == 0) atomicAdd(&g_nsum, red[0]);
}

__global__ void k_ema2(const float* __restrict__ ea, float* __restrict__ out) {
    int i = blockIdx.x * blockDim.x + threadIdx.x;
    if (i < KCB * DDIM) {
        float nea = ea[i] * DECAYF + (1.0f - DECAYF) * g_embed_sum[i];
        out[1 + KCB * DDIM + KCB + i] = nea;
        int k = i >> 6;
        float ncs = out[1 + KCB * DDIM + k];
        float n = g_nsum;
        float smoothed = (ncs + EPSF) / (n + (float)KCB * EPSF) * n;
        out[1 + i] = nea / smoothed;
    }
    if (i == 0) out[0] = g_qerr / (float)NTOK;
}

extern "C" void kernel_launch(void* const* d_in, const int* in_sizes, int n_in,
                              void* d_out, int out_size) {
    const float* z  = (const float*)d_in[0];
    const float* w  = (const float*)d_in[1];
    const float* cs = (const float*)d_in[2];
    const float* ea = (const float*)d_in[3];
    float* out = (float*)d_out;

    cudaFuncSetAttribute(k_main_tc, cudaFuncAttributeMaxDynamicSharedMemorySize, SMEM_TC);

    k_zero<<<(KCB * DDIM + 255) / 256, 256>>>();
    k_cnorm<<<KCB / 8, 256>>>(w);
    k_prep<<<(128 * KCB + 255) / 256, 256>>>(w);
    k_main_tc<<<NTOK / 128, 512, SMEM_TC>>>(z);
    k_scatter<<<NTOK / 8, 256>>>(z, w);
    k_ema1<<<KCB / 256, 256>>>(cs, out);
    k_ema2<<<(KCB * DDIM + 255) / 256, 256>>>(ea, out);
}

// round 8
// speedup vs baseline: 2.6890x; 2.6890x over previous
#include <cuda_runtime.h>
#include <cuda_fp16.h>
#include <cstdint>

#define NTOK 65536
#define KCB  8192
#define DDIM 64
#define DECAYF 0.9f
#define EPSF 1e-5f

// ---- scratch (no allocation allowed) ----
__device__ float g_cnorm[KCB];
__device__ int   g_token[NTOK];
__device__ float g_counts[KCB];
__device__ float g_embed_sum[KCB * DDIM];
__device__ float g_qerr;
__device__ float g_nsum;
// packed fp16x2 split codebook, k-pair-major: g_w2t[kp][c]
// kp 0..31 = (wh[2kp],wh[2kp+1]); kp 32..63 = (wl[2kp-64...]) lo parts
__device__ __align__(16) uint32_t g_w2t[(size_t)64 * KCB];

// ================= helpers =================
__device__ __forceinline__ uint32_t smem_u32(const void* p) {
    uint32_t a;
    asm("{ .reg .u64 t; cvta.to.shared.u64 t, %1; cvt.u32.u64 %0, t; }" : "=r"(a) : "l"(p));
    return a;
}
__device__ __forceinline__ void cp16(uint32_t dst, const void* src) {
    asm volatile("cp.async.ca.shared.global [%0], [%1], 16;" :: "r"(dst), "l"(src));
}
__device__ __forceinline__ uint32_t packh2(float a, float b) {
    __half2 h = __halves2half2(__float2half_rn(a), __float2half_rn(b));
    return *reinterpret_cast<uint32_t*>(&h);
}
__device__ __forceinline__ void mma16(float* c, const uint32_t* a, uint32_t b0, uint32_t b1) {
    asm volatile("mma.sync.aligned.m16n8k16.row.col.f32.f16.f16.f32 "
        "{%0,%1,%2,%3},{%4,%5,%6,%7},{%8,%9},{%0,%1,%2,%3};"
        : "+f"(c[0]), "+f"(c[1]), "+f"(c[2]), "+f"(c[3])
        : "r"(a[0]), "r"(a[1]), "r"(a[2]), "r"(a[3]), "r"(b0), "r"(b1));
}

// ================= small kernels =================
__global__ void k_zero() {
    int i = blockIdx.x * blockDim.x + threadIdx.x;
    if (i < KCB * DDIM) g_embed_sum[i] = 0.0f;
    if (i < KCB)        g_counts[i]    = 0.0f;
    if (i == 0) { g_qerr = 0.0f; g_nsum = 0.0f; }
}

__global__ void k_cnorm(const float* __restrict__ w) {
    int warp = (blockIdx.x * blockDim.x + threadIdx.x) >> 5;
    int lane = threadIdx.x & 31;
    if (warp >= KCB) return;
    float v0 = w[warp * DDIM + lane];
    float v1 = w[warp * DDIM + 32 + lane];
    float s = v0 * v0 + v1 * v1;
    #pragma unroll
    for (int o = 16; o; o >>= 1) s += __shfl_xor_sync(0xffffffffu, s, o);
    if (lane == 0) g_cnorm[warp] = s;
}

// build g_w2t: hi pairs (kp<32) and lo pairs (kp>=32), code-contiguous rows
__global__ void k_prep(const float* __restrict__ w) {
    int i = blockIdx.x * blockDim.x + threadIdx.x;
    if (i >= 64 * KCB) return;
    int kp = i >> 13, c = i & (KCB - 1);
    int d = 2 * (kp & 31);
    float x0 = w[(size_t)c * DDIM + d];
    float x1 = w[(size_t)c * DDIM + d + 1];
    float h0 = __half2float(__float2half_rn(x0));
    float h1 = __half2float(__float2half_rn(x1));
    g_w2t[i] = (kp < 32) ? packh2(x0, x1) : packh2(x0 - h0, x1 - h1);
}

// ================= main tensor-core kernel (fp16x3, mma m16n8k16) =================
static constexpr int AST   = 68;                       // A row stride (uint32)
static constexpr int BST   = 72;                       // B kp-row stride (uint32)
static constexpr int SM_A  = 0;                        // 128*68*4 = 34816
static constexpr int SM_B  = 34816;
static constexpr int B_BUF = 64 * BST * 4;             // 18432
static constexpr int SM_CN = SM_B + 3 * B_BUF;         // 90112
static constexpr int SMEM_TC = SM_CN + KCB * 4;        // 122880

__global__ __launch_bounds__(256, 1) void k_main_tc(const float* __restrict__ z) {
    extern __shared__ char smem[];
    uint32_t* Au = (uint32_t*)(smem + SM_A);
    uint32_t* Bu = (uint32_t*)(smem + SM_B);
    float*    CN = (float*)(smem + SM_CN);
    const uint32_t sbB = smem_u32(Bu);

    const int tid  = threadIdx.x;
    const int lane = tid & 31, wid = tid >> 5;
    const int g    = lane >> 2, tg = lane & 3;
    const int wr   = wid & 3,  wc = wid >> 2;          // 4 token-rows x 2 code-cols
    const int tok0 = blockIdx.x * 128;

    // ---- prologue prefetch of B tiles 0,1 (each 64 codes x 64 kp) ----
    #pragma unroll
    for (int pt = 0; pt < 2; pt++) {
        const uint32_t dstb = sbB + (uint32_t)pt * B_BUF;
        const uint32_t* srcb = g_w2t + pt * 64;
        #pragma unroll
        for (int i = 0; i < 4; i++) {
            int q = i * 256 + tid;                     // 1024 x 16B
            int kp = q >> 4, seg = q & 15;
            cp16(dstb + (uint32_t)(kp * BST + seg * 4) * 4,
                 srcb + (size_t)kp * KCB + seg * 4);
        }
        asm volatile("cp.async.commit_group;");
    }

    // ---- all ||c||^2 into smem ----
    #pragma unroll
    for (int i = 0; i < 8; i++) {
        int q = i * 256 + tid;
        *(float4*)(CN + q * 4) = *(const float4*)(g_cnorm + q * 4);
    }
    // ---- stage A: fp16 split, kp-major: hi kp 0..31, lo kp 32..63 ----
    #pragma unroll
    for (int i = 0; i < 8; i++) {
        int q = i * 256 + tid;                         // 2048 float4
        int row = q >> 4, c4 = q & 15;
        float4 v = *(const float4*)(z + (size_t)(tok0 + row) * DDIM + c4 * 4);
        float hx = __half2float(__float2half_rn(v.x));
        float hy = __half2float(__float2half_rn(v.y));
        float hz = __half2float(__float2half_rn(v.z));
        float hw = __half2float(__float2half_rn(v.w));
        uint32_t* dst = Au + row * AST + 2 * c4;
        dst[0]  = packh2(v.x, v.y);
        dst[1]  = packh2(v.z, v.w);
        dst[32] = packh2(v.x - hx, v.y - hy);
        dst[33] = packh2(v.z - hz, v.w - hw);
    }

    float bv[4];  int bix[4];
    #pragma unroll
    for (int r = 0; r < 4; r++) { bv[r] = 3.4e38f; bix[r] = 0; }

    const uint32_t* arow = Au + (wr * 32 + g) * AST;

    for (int t = 0; t < 128; t++) {
        if (t < 127) asm volatile("cp.async.wait_group 1;");
        else         asm volatile("cp.async.wait_group 0;");
        __syncthreads();
        if (t + 2 < 128) {
            const uint32_t dstb = sbB + (uint32_t)((t + 2) % 3) * B_BUF;
            const uint32_t* srcb = g_w2t + (t + 2) * 64;
            #pragma unroll
            for (int i = 0; i < 4; i++) {
                int q = i * 256 + tid;
                int kp = q >> 4, seg = q & 15;
                cp16(dstb + (uint32_t)(kp * BST + seg * 4) * 4,
                     srcb + (size_t)kp * KCB + seg * 4);
            }
            asm volatile("cp.async.commit_group;");
        }

        const uint32_t* B = Bu + (t % 3) * (64 * BST);
        float acc[2][4][4];
        #pragma unroll
        for (int m = 0; m < 2; m++)
            #pragma unroll
            for (int nt = 0; nt < 4; nt++)
                #pragma unroll
                for (int c = 0; c < 4; c++) acc[m][nt][c] = 0.0f;

        // 12 k16-steps: (zh.wh)x4, (zh.wl)x4, (zl.wh)x4
        #pragma unroll
        for (int s = 0; s < 12; s++) {
            const int term = s >> 2, j = s & 3;
            const int ab = ((term == 2) ? 32 : 0) + 8 * j;
            const int bb = ((term == 1) ? 32 : 0) + 8 * j;
            uint32_t a[2][4];
            #pragma unroll
            for (int m = 0; m < 2; m++) {
                const uint32_t* ap = arow + m * 16 * AST + ab + tg;
                a[m][0] = ap[0];
                a[m][1] = ap[8 * AST];
                a[m][2] = ap[4];
                a[m][3] = ap[8 * AST + 4];
            }
            #pragma unroll
            for (int nt = 0; nt < 4; nt++) {
                const uint32_t* bp = B + (bb + tg) * BST + wc * 32 + nt * 8 + g;
                uint32_t b0 = bp[0];
                uint32_t b1 = bp[4 * BST];
                mma16(acc[0][nt], a[0], b0, b1);
                mma16(acc[1][nt], a[1], b0, b1);
            }
        }

        // epilogue: dist = cn - 2*dot, running argmin (ascending codes = first-min)
        const int cb = t * 64;
        #pragma unroll
        for (int nt = 0; nt < 4; nt++) {
            const int col = cb + wc * 32 + nt * 8 + 2 * tg;
            const float cn0 = CN[col], cn1 = CN[col + 1];
            #pragma unroll
            for (int m = 0; m < 2; m++) {
                #pragma unroll
                for (int h = 0; h < 2; h++) {
                    const int r = m * 2 + h;
                    float d0 = fmaf(-2.0f, acc[m][nt][h * 2 + 0], cn0);
                    float d1 = fmaf(-2.0f, acc[m][nt][h * 2 + 1], cn1);
                    if (d0 < bv[r]) { bv[r] = d0; bix[r] = col; }
                    if (d1 < bv[r]) { bv[r] = d1; bix[r] = col + 1; }
                }
            }
        }
    }

    // combine across quad lanes (same token rows), tie-break smaller index
    #pragma unroll
    for (int r = 0; r < 4; r++) {
        float v = bv[r]; int ix = bix[r];
        #pragma unroll
        for (int o = 1; o < 4; o <<= 1) {
            float v2 = __shfl_xor_sync(0xffffffffu, v, o);
            int   i2 = __shfl_xor_sync(0xffffffffu, ix, o);
            if (v2 < v || (v2 == v && i2 < ix)) { v = v2; ix = i2; }
        }
        bv[r] = v; bix[r] = ix;
    }
    __syncthreads();
    float* sv = (float*)Bu;
    int*   si = (int*)(Bu + 256);
    if (tg == 0) {
        #pragma unroll
        for (int m = 0; m < 2; m++)
            #pragma unroll
            for (int h = 0; h < 2; h++) {
                int row = wr * 32 + m * 16 + g + 8 * h;
                sv[wc * 128 + row] = bv[m * 2 + h];
                si[wc * 128 + row] = bix[m * 2 + h];
            }
    }
    __syncthreads();
    if (tid < 128) {
        float v0 = sv[tid], v1 = sv[128 + tid];
        int   i0 = si[tid], i1 = si[128 + tid];
        g_token[tok0 + tid] = (v1 < v0 || (v1 == v0 && i1 < i0)) ? i1 : i0;
    }
}

// ---------------- scatter: counts, embed_sum, quant error ----------------
__global__ void k_scatter(const float* __restrict__ z, const float* __restrict__ w) {
    __shared__ float qs[8];
    int warp = threadIdx.x >> 5;
    int lane = threadIdx.x & 31;
    int n = blockIdx.x * 8 + warp;
    int k = g_token[n];
    float z0 = z[(size_t)n * DDIM + lane];
    float z1 = z[(size_t)n * DDIM + 32 + lane];
    float w0 = w[(size_t)k * DDIM + lane];
    float w1 = w[(size_t)k * DDIM + 32 + lane];
    atomicAdd(&g_embed_sum[k * DDIM + lane], z0);
    atomicAdd(&g_embed_sum[k * DDIM + 32 + lane], z1);
    float d0 = w0 - z0, d1 = w1 - z1;
    float s = d0 * d0 + d1 * d1;
    #pragma unroll
    for (int o = 16; o; o >>= 1) s += __shfl_xor_sync(0xffffffffu, s, o);
    if (lane == 0) { qs[warp] = s; atomicAdd(&g_counts[k], 1.0f); }
    __syncthreads();
    if (threadIdx.x == 0) {
        float t = 0.0f;
        #pragma unroll
        for (int i = 0; i < 8; i++) t += qs[i];
        atomicAdd(&g_qerr, t);
    }
}

__global__ void k_ema1(const float* __restrict__ cs, float* __restrict__ out) {
    __shared__ float red[256];
    int k = blockIdx.x * blockDim.x + threadIdx.x;
    float ncs = cs[k] * DECAYF + (1.0f - DECAYF) * g_counts[k];
    out[1 + KCB * DDIM + k] = ncs;
    red[threadIdx.x] = ncs;
    __syncthreads();
    for (int s = 128; s; s >>= 1) {
        if (threadIdx.x < s) red[threadIdx.x] += red[threadIdx.x + s];
        __syncthreads();
    }
    if (threadIdx.x == 0) atomicAdd(&g_nsum, red[0]);
}

__global__ void k_ema2(const float* __restrict__ ea, float* __restrict__ out) {
    int i = blockIdx.x * blockDim.x + threadIdx.x;
    if (i < KCB * DDIM) {
        float nea = ea[i] * DECAYF + (1.0f - DECAYF) * g_embed_sum[i];
        out[1 + KCB * DDIM + KCB + i] = nea;
        int k = i >> 6;
        float ncs = out[1 + KCB * DDIM + k];
        float n = g_nsum;
        float smoothed = (ncs + EPSF) / (n + (float)KCB * EPSF) * n;
        out[1 + i] = nea / smoothed;
    }
    if (i == 0) out[0] = g_qerr / (float)NTOK;
}

extern "C" void kernel_launch(void* const* d_in, const int* in_sizes, int n_in,
                              void* d_out, int out_size) {
    const float* z  = (const float*)d_in[0];
    const float* w  = (const float*)d_in[1];
    const float* cs = (const float*)d_in[2];
    const float* ea = (const float*)d_in[3];
    float* out = (float*)d_out;

    cudaFuncSetAttribute(k_main_tc, cudaFuncAttributeMaxDynamicSharedMemorySize, SMEM_TC);

    k_zero<<<(KCB * DDIM + 255) / 256, 256>>>();
    k_cnorm<<<KCB / 8, 256>>>(w);
    k_prep<<<(64 * KCB + 255) / 256, 256>>>(w);
    k_main_tc<<<NTOK / 128, 256, SMEM_TC>>>(z);
    k_scatter<<<NTOK / 8, 256>>>(z, w);
    k_ema1<<<KCB / 256, 256>>>(cs, out);
    k_ema2<<<(KCB * DDIM + 255) / 256, 256>>>(ea, out);
}

// round 9
// speedup vs baseline: 2.8394x; 1.0559x over previous
#include <cuda_runtime.h>
#include <cuda_fp16.h>
#include <cstdint>

#define NTOK 65536
#define KCB  8192
#define DDIM 64
#define DECAYF 0.9f
#define EPSF 1e-5f

// ---- scratch (no allocation allowed) ----
__device__ float g_cnorm[KCB];
__device__ int   g_token[NTOK];
__device__ float g_counts[KCB];
__device__ float g_embed_sum[KCB * DDIM];
__device__ float g_qerr;
__device__ float g_nsum;
// packed fp16x2 split codebook, k-pair-major: g_w2t[kp][c]
__device__ __align__(16) uint32_t g_w2t[(size_t)64 * KCB];

// ================= helpers =================
__device__ __forceinline__ uint32_t smem_u32(const void* p) {
    uint32_t a;
    asm("{ .reg .u64 t; cvta.to.shared.u64 t, %1; cvt.u32.u64 %0, t; }" : "=r"(a) : "l"(p));
    return a;
}
__device__ __forceinline__ void cp16(uint32_t dst, const void* src) {
    asm volatile("cp.async.ca.shared.global [%0], [%1], 16;" :: "r"(dst), "l"(src));
}
__device__ __forceinline__ uint32_t packh2(float a, float b) {
    __half2 h = __halves2half2(__float2half_rn(a), __float2half_rn(b));
    return *reinterpret_cast<uint32_t*>(&h);
}
__device__ __forceinline__ void mma16(float* c, const uint32_t* a, uint32_t b0, uint32_t b1) {
    asm volatile("mma.sync.aligned.m16n8k16.row.col.f32.f16.f16.f32 "
        "{%0,%1,%2,%3},{%4,%5,%6,%7},{%8,%9},{%0,%1,%2,%3};"
        : "+f"(c[0]), "+f"(c[1]), "+f"(c[2]), "+f"(c[3])
        : "r"(a[0]), "r"(a[1]), "r"(a[2]), "r"(a[3]), "r"(b0), "r"(b1));
}

// ================= small kernels =================
__global__ void k_zero() {
    int i = blockIdx.x * blockDim.x + threadIdx.x;
    if (i < KCB * DDIM) g_embed_sum[i] = 0.0f;
    if (i < KCB)        g_counts[i]    = 0.0f;
    if (i == 0) { g_qerr = 0.0f; g_nsum = 0.0f; }
}

__global__ void k_cnorm(const float* __restrict__ w) {
    int warp = (blockIdx.x * blockDim.x + threadIdx.x) >> 5;
    int lane = threadIdx.x & 31;
    if (warp >= KCB) return;
    float v0 = w[warp * DDIM + lane];
    float v1 = w[warp * DDIM + 32 + lane];
    float s = v0 * v0 + v1 * v1;
    #pragma unroll
    for (int o = 16; o; o >>= 1) s += __shfl_xor_sync(0xffffffffu, s, o);
    if (lane == 0) g_cnorm[warp] = s;
}

// build g_w2t: hi pairs (kp<32) and lo pairs (kp>=32), code-contiguous rows
__global__ void k_prep(const float* __restrict__ w) {
    int i = blockIdx.x * blockDim.x + threadIdx.x;
    if (i >= 64 * KCB) return;
    int kp = i >> 13, c = i & (KCB - 1);
    int d = 2 * (kp & 31);
    float x0 = w[(size_t)c * DDIM + d];
    float x1 = w[(size_t)c * DDIM + d + 1];
    float h0 = __half2float(__float2half_rn(x0));
    float h1 = __half2float(__float2half_rn(x1));
    g_w2t[i] = (kp < 32) ? packh2(x0, x1) : packh2(x0 - h0, x1 - h1);
}

// ================= main tensor-core kernel (fp16x3, 2 CTAs/SM) =================
static constexpr int AST   = 68;                       // A row stride (uint32)
static constexpr int BST   = 72;                       // B kp-row stride (uint32)
static constexpr int SM_A  = 0;                        // 128*68*4 = 34816
static constexpr int SM_B  = 34816;
static constexpr int B_BUF = 64 * BST * 4;             // 18432
static constexpr int SMEM_TC = SM_B + 3 * B_BUF;       // 90112

__global__ __launch_bounds__(256, 2) void k_main_tc(const float* __restrict__ z) {
    extern __shared__ char smem[];
    uint32_t* Au = (uint32_t*)(smem + SM_A);
    uint32_t* Bu = (uint32_t*)(smem + SM_B);
    const uint32_t sbB = smem_u32(Bu);

    const int tid  = threadIdx.x;
    const int lane = tid & 31, wid = tid >> 5;
    const int g    = lane >> 2, tg = lane & 3;
    const int wr   = wid & 3,  wc = wid >> 2;          // 4 token-rows x 2 code-cols
    const int tok0 = blockIdx.x * 128;

    // ---- prologue prefetch of B tiles 0,1 (each 64 codes x 64 kp) ----
    #pragma unroll
    for (int pt = 0; pt < 2; pt++) {
        const uint32_t dstb = sbB + (uint32_t)pt * B_BUF;
        const uint32_t* srcb = g_w2t + pt * 64;
        #pragma unroll
        for (int i = 0; i < 4; i++) {
            int q = i * 256 + tid;                     // 1024 x 16B
            int kp = q >> 4, seg = q & 15;
            cp16(dstb + (uint32_t)(kp * BST + seg * 4) * 4,
                 srcb + (size_t)kp * KCB + seg * 4);
        }
        asm volatile("cp.async.commit_group;");
    }

    // ---- stage A: fp16 split, kp-major: hi kp 0..31, lo kp 32..63 ----
    #pragma unroll
    for (int i = 0; i < 8; i++) {
        int q = i * 256 + tid;                         // 2048 float4
        int row = q >> 4, c4 = q & 15;
        float4 v = *(const float4*)(z + (size_t)(tok0 + row) * DDIM + c4 * 4);
        float hx = __half2float(__float2half_rn(v.x));
        float hy = __half2float(__float2half_rn(v.y));
        float hz = __half2float(__float2half_rn(v.z));
        float hw = __half2float(__float2half_rn(v.w));
        uint32_t* dst = Au + row * AST + 2 * c4;
        dst[0]  = packh2(v.x, v.y);
        dst[1]  = packh2(v.z, v.w);
        dst[32] = packh2(v.x - hx, v.y - hy);
        dst[33] = packh2(v.z - hz, v.w - hw);
    }

    float bv[4];  int bix[4];
    #pragma unroll
    for (int r = 0; r < 4; r++) { bv[r] = 3.4e38f; bix[r] = 0; }

    const uint32_t* arow = Au + (wr * 32 + g) * AST;

    for (int t = 0; t < 128; t++) {
        if (t < 127) asm volatile("cp.async.wait_group 1;");
        else         asm volatile("cp.async.wait_group 0;");
        __syncthreads();
        if (t + 2 < 128) {
            const uint32_t dstb = sbB + (uint32_t)((t + 2) % 3) * B_BUF;
            const uint32_t* srcb = g_w2t + (t + 2) * 64;
            #pragma unroll
            for (int i = 0; i < 4; i++) {
                int q = i * 256 + tid;
                int kp = q >> 4, seg = q & 15;
                cp16(dstb + (uint32_t)(kp * BST + seg * 4) * 4,
                     srcb + (size_t)kp * KCB + seg * 4);
            }
            asm volatile("cp.async.commit_group;");
        }

        const uint32_t* B = Bu + (t % 3) * (64 * BST);
        float acc[2][4][4];
        #pragma unroll
        for (int m = 0; m < 2; m++)
            #pragma unroll
            for (int nt = 0; nt < 4; nt++)
                #pragma unroll
                for (int c = 0; c < 4; c++) acc[m][nt][c] = 0.0f;

        // 12 k16-steps: (zh.wh)x4, (zh.wl)x4, (zl.wh)x4
        #pragma unroll
        for (int s = 0; s < 12; s++) {
            const int term = s >> 2, j = s & 3;
            const int ab = ((term == 2) ? 32 : 0) + 8 * j;
            const int bb = ((term == 1) ? 32 : 0) + 8 * j;
            uint32_t a[2][4];
            #pragma unroll
            for (int m = 0; m < 2; m++) {
                const uint32_t* ap = arow + m * 16 * AST + ab + tg;
                a[m][0] = ap[0];
                a[m][1] = ap[8 * AST];
                a[m][2] = ap[4];
                a[m][3] = ap[8 * AST + 4];
            }
            #pragma unroll
            for (int nt = 0; nt < 4; nt++) {
                const uint32_t* bp = B + (bb + tg) * BST + wc * 32 + nt * 8 + g;
                uint32_t b0 = bp[0];
                uint32_t b1 = bp[4 * BST];
                mma16(acc[0][nt], a[0], b0, b1);
                mma16(acc[1][nt], a[1], b0, b1);
            }
        }

        // epilogue: dist = cn - 2*dot, running argmin (ascending codes = first-min)
        const int cb = t * 64;
        #pragma unroll
        for (int nt = 0; nt < 4; nt++) {
            const int col = cb + wc * 32 + nt * 8 + 2 * tg;
            const float2 c2 = __ldg((const float2*)(g_cnorm + col));
            #pragma unroll
            for (int m = 0; m < 2; m++) {
                #pragma unroll
                for (int h = 0; h < 2; h++) {
                    const int r = m * 2 + h;
                    float d0 = fmaf(-2.0f, acc[m][nt][h * 2 + 0], c2.x);
                    float d1 = fmaf(-2.0f, acc[m][nt][h * 2 + 1], c2.y);
                    if (d0 < bv[r]) { bv[r] = d0; bix[r] = col; }
                    if (d1 < bv[r]) { bv[r] = d1; bix[r] = col + 1; }
                }
            }
        }
    }

    // combine across quad lanes (same token rows), tie-break smaller index
    #pragma unroll
    for (int r = 0; r < 4; r++) {
        float v = bv[r]; int ix = bix[r];
        #pragma unroll
        for (int o = 1; o < 4; o <<= 1) {
            float v2 = __shfl_xor_sync(0xffffffffu, v, o);
            int   i2 = __shfl_xor_sync(0xffffffffu, ix, o);
            if (v2 < v || (v2 == v && i2 < ix)) { v = v2; ix = i2; }
        }
        bv[r] = v; bix[r] = ix;
    }
    __syncthreads();
    float* sv = (float*)Bu;
    int*   si = (int*)(Bu + 256);
    if (tg == 0) {
        #pragma unroll
        for (int m = 0; m < 2; m++)
            #pragma unroll
            for (int h = 0; h < 2; h++) {
                int row = wr * 32 + m * 16 + g + 8 * h;
                sv[wc * 128 + row] = bv[m * 2 + h];
                si[wc * 128 + row] = bix[m * 2 + h];
            }
    }
    __syncthreads();
    if (tid < 128) {
        float v0 = sv[tid], v1 = sv[128 + tid];
        int   i0 = si[tid], i1 = si[128 + tid];
        g_token[tok0 + tid] = (v1 < v0 || (v1 == v0 && i1 < i0)) ? i1 : i0;
    }
}

// ---------------- scatter: counts, embed_sum, quant error ----------------
__global__ void k_scatter(const float* __restrict__ z, const float* __restrict__ w) {
    __shared__ float qs[8];
    int warp = threadIdx.x >> 5;
    int lane = threadIdx.x & 31;
    int n = blockIdx.x * 8 + warp;
    int k = g_token[n];
    float z0 = z[(size_t)n * DDIM + lane];
    float z1 = z[(size_t)n * DDIM + 32 + lane];
    float w0 = w[(size_t)k * DDIM + lane];
    float w1 = w[(size_t)k * DDIM + 32 + lane];
    atomicAdd(&g_embed_sum[k * DDIM + lane], z0);
    atomicAdd(&g_embed_sum[k * DDIM + 32 + lane], z1);
    float d0 = w0 - z0, d1 = w1 - z1;
    float s = d0 * d0 + d1 * d1;
    #pragma unroll
    for (int o = 16; o; o >>= 1) s += __shfl_xor_sync(0xffffffffu, s, o);
    if (lane == 0) { qs[warp] = s; atomicAdd(&g_counts[k], 1.0f); }
    __syncthreads();
    if (threadIdx.x == 0) {
        float t = 0.0f;
        #pragma unroll
        for (int i = 0; i < 8; i++) t += qs[i];
        atomicAdd(&g_qerr, t);
    }
}

__global__ void k_ema1(const float* __restrict__ cs, float* __restrict__ out) {
    __shared__ float red[256];
    int k = blockIdx.x * blockDim.x + threadIdx.x;
    float ncs = cs[k] * DECAYF + (1.0f - DECAYF) * g_counts[k];
    out[1 + KCB * DDIM + k] = ncs;
    red[threadIdx.x] = ncs;
    __syncthreads();
    for (int s = 128; s; s >>= 1) {
        if (threadIdx.x < s) red[threadIdx.x] += red[threadIdx.x + s];
        __syncthreads();
    }
    if (threadIdx.x == 0) atomicAdd(&g_nsum, red[0]);
}

__global__ void k_ema2(const float* __restrict__ ea, float* __restrict__ out) {
    int i = blockIdx.x * blockDim.x + threadIdx.x;
    if (i < KCB * DDIM) {
        float nea = ea[i] * DECAYF + (1.0f - DECAYF) * g_embed_sum[i];
        out[1 + KCB * DDIM + KCB + i] = nea;
        int k = i >> 6;
        float ncs = out[1 + KCB * DDIM + k];
        float n = g_nsum;
        float smoothed = (ncs + EPSF) / (n + (float)KCB * EPSF) * n;
        out[1 + i] = nea / smoothed;
    }
    if (i == 0) out[0] = g_qerr / (float)NTOK;
}

extern "C" void kernel_launch(void* const* d_in, const int* in_sizes, int n_in,
                              void* d_out, int out_size) {
    const float* z  = (const float*)d_in[0];
    const float* w  = (const float*)d_in[1];
    const float* cs = (const float*)d_in[2];
    const float* ea = (const float*)d_in[3];
    float* out = (float*)d_out;

    cudaFuncSetAttribute(k_main_tc, cudaFuncAttributeMaxDynamicSharedMemorySize, SMEM_TC);

    k_zero<<<(KCB * DDIM + 255) / 256, 256>>>();
    k_cnorm<<<KCB / 8, 256>>>(w);
    k_prep<<<(64 * KCB + 255) / 256, 256>>>(w);
    k_main_tc<<<NTOK / 128, 256, SMEM_TC>>>(z);
    k_scatter<<<NTOK / 8, 256>>>(z, w);
    k_ema1<<<KCB / 256, 256>>>(cs, out);
    k_ema2<<<(KCB * DDIM + 255) / 256, 256>>>(ea, out);
}

// round 10
// speedup vs baseline: 3.1924x; 1.1243x over previous
#include <cuda_runtime.h>
#include <cuda_fp16.h>
#include <cstdint>

#define NTOK 65536
#define KCB  8192
#define DDIM 64
#define DECAYF 0.9f
#define EPSF 1e-5f

// ---- scratch (no allocation allowed) ----
__device__ float g_cnorm[KCB];
__device__ int   g_token[NTOK];
__device__ float g_counts[KCB];
__device__ float g_embed_sum[KCB * DDIM];
__device__ float g_qerr;
__device__ float g_nsum;
// packed fp16x2 split codebook, k-pair-major: g_w2t[kp][c]
__device__ __align__(16) uint32_t g_w2t[(size_t)64 * KCB];

// ================= helpers =================
__device__ __forceinline__ uint32_t smem_u32(const void* p) {
    uint32_t a;
    asm("{ .reg .u64 t; cvta.to.shared.u64 t, %1; cvt.u32.u64 %0, t; }" : "=r"(a) : "l"(p));
    return a;
}
__device__ __forceinline__ void cp16(uint32_t dst, const void* src) {
    asm volatile("cp.async.ca.shared.global [%0], [%1], 16;" :: "r"(dst), "l"(src));
}
__device__ __forceinline__ uint32_t packh2(float a, float b) {
    __half2 h = __halves2half2(__float2half_rn(a), __float2half_rn(b));
    return *reinterpret_cast<uint32_t*>(&h);
}
__device__ __forceinline__ void mma16(float* c, const uint32_t* a, uint32_t b0, uint32_t b1) {
    asm volatile("mma.sync.aligned.m16n8k16.row.col.f32.f16.f16.f32 "
        "{%0,%1,%2,%3},{%4,%5,%6,%7},{%8,%9},{%0,%1,%2,%3};"
        : "+f"(c[0]), "+f"(c[1]), "+f"(c[2]), "+f"(c[3])
        : "r"(a[0]), "r"(a[1]), "r"(a[2]), "r"(a[3]), "r"(b0), "r"(b1));
}

// ================= small kernels =================
__global__ void k_zero() {
    int i = blockIdx.x * blockDim.x + threadIdx.x;
    if (i < KCB * DDIM) g_embed_sum[i] = 0.0f;
    if (i < KCB)        g_counts[i]    = 0.0f;
    if (i == 0) { g_qerr = 0.0f; g_nsum = 0.0f; }
}

__global__ void k_cnorm(const float* __restrict__ w) {
    int warp = (blockIdx.x * blockDim.x + threadIdx.x) >> 5;
    int lane = threadIdx.x & 31;
    if (warp >= KCB) return;
    float v0 = w[warp * DDIM + lane];
    float v1 = w[warp * DDIM + 32 + lane];
    float s = v0 * v0 + v1 * v1;
    #pragma unroll
    for (int o = 16; o; o >>= 1) s += __shfl_xor_sync(0xffffffffu, s, o);
    if (lane == 0) g_cnorm[warp] = s;
}

// build g_w2t: hi pairs (kp<32) and lo pairs (kp>=32), code-contiguous rows
__global__ void k_prep(const float* __restrict__ w) {
    int i = blockIdx.x * blockDim.x + threadIdx.x;
    if (i >= 64 * KCB) return;
    int kp = i >> 13, c = i & (KCB - 1);
    int d = 2 * (kp & 31);
    float x0 = w[(size_t)c * DDIM + d];
    float x1 = w[(size_t)c * DDIM + d + 1];
    float h0 = __half2float(__float2half_rn(x0));
    float h1 = __half2float(__float2half_rn(x1));
    g_w2t[i] = (kp < 32) ? packh2(x0, x1) : packh2(x0 - h0, x1 - h1);
}

// ================= main tensor-core kernel (fp16x3, A-resident, 2 CTAs/SM) =================
static constexpr int AST   = 68;                       // A row stride (uint32)
static constexpr int BST   = 72;                       // B kp-row stride (uint32)
static constexpr int SM_A  = 0;                        // 128*68*4 = 34816
static constexpr int SM_B  = 34816;
static constexpr int B_BUF = 64 * BST * 4;             // 18432
static constexpr int SMEM_TC = SM_B + 3 * B_BUF;       // 90112

__global__ __launch_bounds__(256, 2) void k_main_tc(const float* __restrict__ z) {
    extern __shared__ char smem[];
    uint32_t* Au = (uint32_t*)(smem + SM_A);
    uint32_t* Bu = (uint32_t*)(smem + SM_B);
    const uint32_t sbB = smem_u32(Bu);

    const int tid  = threadIdx.x;
    const int lane = tid & 31, wid = tid >> 5;
    const int g    = lane >> 2, tg = lane & 3;
    const int wr   = wid & 3,  wc = wid >> 2;          // 4 token-rows x 2 code-cols
    const int tok0 = blockIdx.x * 128;

    // ---- prologue prefetch of B tiles 0,1 (each 64 codes x 64 kp) ----
    #pragma unroll
    for (int pt = 0; pt < 2; pt++) {
        const uint32_t dstb = sbB + (uint32_t)pt * B_BUF;
        const uint32_t* srcb = g_w2t + pt * 64;
        #pragma unroll
        for (int i = 0; i < 4; i++) {
            int q = i * 256 + tid;                     // 1024 x 16B
            int kp = q >> 4, seg = q & 15;
            cp16(dstb + (uint32_t)(kp * BST + seg * 4) * 4,
                 srcb + (size_t)kp * KCB + seg * 4);
        }
        asm volatile("cp.async.commit_group;");
    }

    // ---- stage A: fp16 split, kp-major: hi kp 0..31, lo kp 32..63 ----
    #pragma unroll
    for (int i = 0; i < 8; i++) {
        int q = i * 256 + tid;                         // 2048 float4
        int row = q >> 4, c4 = q & 15;
        float4 v = *(const float4*)(z + (size_t)(tok0 + row) * DDIM + c4 * 4);
        float hx = __half2float(__float2half_rn(v.x));
        float hy = __half2float(__float2half_rn(v.y));
        float hz = __half2float(__float2half_rn(v.z));
        float hw = __half2float(__float2half_rn(v.w));
        uint32_t* dst = Au + row * AST + 2 * c4;
        dst[0]  = packh2(v.x, v.y);
        dst[1]  = packh2(v.z, v.w);
        dst[32] = packh2(v.x - hx, v.y - hy);
        dst[33] = packh2(v.z - hz, v.w - hw);
    }
    __syncthreads();

    // ---- load ALL A fragments to registers (invariant across tiles) ----
    uint32_t Ah[4][2][4], Al[4][2][4];                 // [j][m][reg]
    {
        const uint32_t* arow = Au + (wr * 32 + g) * AST;
        #pragma unroll
        for (int j = 0; j < 4; j++) {
            #pragma unroll
            for (int m = 0; m < 2; m++) {
                const uint32_t* aph = arow + m * 16 * AST + 8 * j + tg;
                Ah[j][m][0] = aph[0];
                Ah[j][m][1] = aph[8 * AST];
                Ah[j][m][2] = aph[4];
                Ah[j][m][3] = aph[8 * AST + 4];
                const uint32_t* apl = aph + 32;
                Al[j][m][0] = apl[0];
                Al[j][m][1] = apl[8 * AST];
                Al[j][m][2] = apl[4];
                Al[j][m][3] = apl[8 * AST + 4];
            }
        }
    }

    float bv[4];  int bix[4];
    #pragma unroll
    for (int r = 0; r < 4; r++) { bv[r] = 3.4e38f; bix[r] = 0; }

    for (int t = 0; t < 128; t++) {
        if (t < 127) asm volatile("cp.async.wait_group 1;");
        else         asm volatile("cp.async.wait_group 0;");
        __syncthreads();
        if (t + 2 < 128) {
            const uint32_t dstb = sbB + (uint32_t)((t + 2) % 3) * B_BUF;
            const uint32_t* srcb = g_w2t + (t + 2) * 64;
            #pragma unroll
            for (int i = 0; i < 4; i++) {
                int q = i * 256 + tid;
                int kp = q >> 4, seg = q & 15;
                cp16(dstb + (uint32_t)(kp * BST + seg * 4) * 4,
                     srcb + (size_t)kp * KCB + seg * 4);
            }
            asm volatile("cp.async.commit_group;");
        }

        const uint32_t* B = Bu + (t % 3) * (64 * BST);
        float acc[2][4][4];
        #pragma unroll
        for (int m = 0; m < 2; m++)
            #pragma unroll
            for (int nt = 0; nt < 4; nt++)
                #pragma unroll
                for (int c = 0; c < 4; c++) acc[m][nt][c] = 0.0f;

        // per (j,nt): load {bh,bl} once, feed 6 MMAs (zh*wh, zh*wl, zl*wh)
        #pragma unroll
        for (int j = 0; j < 4; j++) {
            const uint32_t* brow = B + (8 * j + tg) * BST + wc * 32 + g;
            #pragma unroll
            for (int nt = 0; nt < 4; nt++) {
                const uint32_t* bph = brow + nt * 8;
                uint32_t bh0 = bph[0];
                uint32_t bh1 = bph[4 * BST];
                uint32_t bl0 = bph[32 * BST];
                uint32_t bl1 = bph[36 * BST];
                mma16(acc[0][nt], Ah[j][0], bh0, bh1);
                mma16(acc[1][nt], Ah[j][1], bh0, bh1);
                mma16(acc[0][nt], Ah[j][0], bl0, bl1);
                mma16(acc[1][nt], Ah[j][1], bl0, bl1);
                mma16(acc[0][nt], Al[j][0], bh0, bh1);
                mma16(acc[1][nt], Al[j][1], bh0, bh1);
            }
        }

        // epilogue: dist = cn - 2*dot, running argmin (ascending codes = first-min)
        const int cb = t * 64;
        #pragma unroll
        for (int nt = 0; nt < 4; nt++) {
            const int col = cb + wc * 32 + nt * 8 + 2 * tg;
            const float2 c2 = __ldg((const float2*)(g_cnorm + col));
            #pragma unroll
            for (int m = 0; m < 2; m++) {
                #pragma unroll
                for (int h = 0; h < 2; h++) {
                    const int r = m * 2 + h;
                    float d0 = fmaf(-2.0f, acc[m][nt][h * 2 + 0], c2.x);
                    float d1 = fmaf(-2.0f, acc[m][nt][h * 2 + 1], c2.y);
                    if (d0 < bv[r]) { bv[r] = d0; bix[r] = col; }
                    if (d1 < bv[r]) { bv[r] = d1; bix[r] = col + 1; }
                }
            }
        }
    }

    // combine across quad lanes (same token rows), tie-break smaller index
    #pragma unroll
    for (int r = 0; r < 4; r++) {
        float v = bv[r]; int ix = bix[r];
        #pragma unroll
        for (int o = 1; o < 4; o <<= 1) {
            float v2 = __shfl_xor_sync(0xffffffffu, v, o);
            int   i2 = __shfl_xor_sync(0xffffffffu, ix, o);
            if (v2 < v || (v2 == v && i2 < ix)) { v = v2; ix = i2; }
        }
        bv[r] = v; bix[r] = ix;
    }
    __syncthreads();
    float* sv = (float*)Bu;
    int*   si = (int*)(Bu + 256);
    if (tg == 0) {
        #pragma unroll
        for (int m = 0; m < 2; m++)
            #pragma unroll
            for (int h = 0; h < 2; h++) {
                int row = wr * 32 + m * 16 + g + 8 * h;
                sv[wc * 128 + row] = bv[m * 2 + h];
                si[wc * 128 + row] = bix[m * 2 + h];
            }
    }
    __syncthreads();
    if (tid < 128) {
        float v0 = sv[tid], v1 = sv[128 + tid];
        int   i0 = si[tid], i1 = si[128 + tid];
        g_token[tok0 + tid] = (v1 < v0 || (v1 == v0 && i1 < i0)) ? i1 : i0;
    }
}

// ---------------- scatter: counts, embed_sum, quant error ----------------
__global__ void k_scatter(const float* __restrict__ z, const float* __restrict__ w) {
    __shared__ float qs[8];
    int warp = threadIdx.x >> 5;
    int lane = threadIdx.x & 31;
    int n = blockIdx.x * 8 + warp;
    int k = g_token[n];
    float z0 = z[(size_t)n * DDIM + lane];
    float z1 = z[(size_t)n * DDIM + 32 + lane];
    float w0 = w[(size_t)k * DDIM + lane];
    float w1 = w[(size_t)k * DDIM + 32 + lane];
    atomicAdd(&g_embed_sum[k * DDIM + lane], z0);
    atomicAdd(&g_embed_sum[k * DDIM + 32 + lane], z1);
    float d0 = w0 - z0, d1 = w1 - z1;
    float s = d0 * d0 + d1 * d1;
    #pragma unroll
    for (int o = 16; o; o >>= 1) s += __shfl_xor_sync(0xffffffffu, s, o);
    if (lane == 0) { qs[warp] = s; atomicAdd(&g_counts[k], 1.0f); }
    __syncthreads();
    if (threadIdx.x == 0) {
        float t = 0.0f;
        #pragma unroll
        for (int i = 0; i < 8; i++) t += qs[i];
        atomicAdd(&g_qerr, t);
    }
}

__global__ void k_ema1(const float* __restrict__ cs, float* __restrict__ out) {
    __shared__ float red[256];
    int k = blockIdx.x * blockDim.x + threadIdx.x;
    float ncs = cs[k] * DECAYF + (1.0f - DECAYF) * g_counts[k];
    out[1 + KCB * DDIM + k] = ncs;
    red[threadIdx.x] = ncs;
    __syncthreads();
    for (int s = 128; s; s >>= 1) {
        if (threadIdx.x < s) red[threadIdx.x] += red[threadIdx.x + s];
        __syncthreads();
    }
    if (threadIdx.x == 0) atomicAdd(&g_nsum, red[0]);
}

__global__ void k_ema2(const float* __restrict__ ea, float* __restrict__ out) {
    int i = blockIdx.x * blockDim.x + threadIdx.x;
    if (i < KCB * DDIM) {
        float nea = ea[i] * DECAYF + (1.0f - DECAYF) * g_embed_sum[i];
        out[1 + KCB * DDIM + KCB + i] = nea;
        int k = i >> 6;
        float ncs = out[1 + KCB * DDIM + k];
        float n = g_nsum;
        float smoothed = (ncs + EPSF) / (n + (float)KCB * EPSF) * n;
        out[1 + i] = nea / smoothed;
    }
    if (i == 0) out[0] = g_qerr / (float)NTOK;
}

extern "C" void kernel_launch(void* const* d_in, const int* in_sizes, int n_in,
                              void* d_out, int out_size) {
    const float* z  = (const float*)d_in[0];
    const float* w  = (const float*)d_in[1];
    const float* cs = (const float*)d_in[2];
    const float* ea = (const float*)d_in[3];
    float* out = (float*)d_out;

    cudaFuncSetAttribute(k_main_tc, cudaFuncAttributeMaxDynamicSharedMemorySize, SMEM_TC);

    k_zero<<<(KCB * DDIM + 255) / 256, 256>>>();
    k_cnorm<<<KCB / 8, 256>>>(w);
    k_prep<<<(64 * KCB + 255) / 256, 256>>>(w);
    k_main_tc<<<NTOK / 128, 256, SMEM_TC>>>(z);
    k_scatter<<<NTOK / 8, 256>>>(z, w);
    k_ema1<<<KCB / 256, 256>>>(cs, out);
    k_ema2<<<(KCB * DDIM + 255) / 256, 256>>>(ea, out);
}